// round 4
// baseline (speedup 1.0000x reference)
#include <cuda_runtime.h>
#include <math.h>

// Pure streaming zero-fill: one float4 store per thread, no branches beyond
// the bounds check, no integer divides. This is the bandwidth-floor shape.
__global__ void nkat_zero_kernel(float4* __restrict__ out, unsigned total4) {
    unsigned idx4 = blockIdx.x * blockDim.x + threadIdx.x;
    if (idx4 < total4)
        out[idx4] = make_float4(0.f, 0.f, 0.f, 0.f);
}

// Diagonal: d scattered 4B stores (d = 8192) — negligible.
__global__ void nkat_diag_kernel(float* __restrict__ out,
                                 const float* __restrict__ h, int d) {
    int r = blockIdx.x * blockDim.x + threadIdx.x;
    if (r < d)
        out[(long long)r * d + r] = __ldg(&h[r]);
}

// Scatter V[k]*scale into (i,j) and (j,i). Indices are unique -> plain stores,
// no atomics. Robust to int32 vs int64 index storage: for little-endian int64
// with i >= 1 (strict lower triangle), the int32 view's element[1] is the high
// word of i_0, i.e. 0; for int32 storage it is i_1 >= 1.
__global__ void nkat_scatter_kernel(float* __restrict__ out,
                                    const float* __restrict__ V,
                                    const int* __restrict__ idx32,
                                    int m, int d, float scale) {
    int k = blockIdx.x * blockDim.x + threadIdx.x;
    if (k >= m) return;
    const bool is64 = (__ldg(&idx32[1]) == 0);   // broadcast load, L2-cached
    int i, j;
    if (is64) {
        i = __ldg(&idx32[2 * k]);            // low word of int64 i_k
        j = __ldg(&idx32[2 * m + 2 * k]);    // row 1 starts at int64 offset m
    } else {
        i = __ldg(&idx32[k]);
        j = __ldg(&idx32[m + k]);
    }
    float v = __ldg(&V[k]) * scale;
    out[(long long)i * d + j] = v;
    out[(long long)j * d + i] = v;
}

extern "C" void kernel_launch(void* const* d_in, const int* in_sizes, int n_in,
                              void* d_out, int out_size) {
    // metadata order: h_local [d] f32, V_interaction [m] f32,
    //                 interaction_indices [2,m] int, dimension (scalar, unused)
    const float* h   = (const float*)d_in[0];
    const float* V   = (const float*)d_in[1];
    const int*   idx = (const int*)d_in[2];
    float* out = (float*)d_out;

    const int d = in_sizes[0];
    const int m = in_sizes[1];

    const float scale = (float)(1.0 - 0.2 / sqrt(log((double)d)));

    const unsigned total4 = (unsigned)(((long long)d * d) >> 2);  // 16M float4

    {
        const int threads = 256;
        const int blocks  = (int)((total4 + threads - 1) / threads);
        nkat_zero_kernel<<<blocks, threads>>>((float4*)out, total4);
    }
    {
        const int threads = 256;
        const int blocks  = (d + threads - 1) / threads;
        nkat_diag_kernel<<<blocks, threads>>>(out, h, d);
    }
    {
        const int threads = 256;
        const int blocks  = (m + threads - 1) / threads;
        nkat_scatter_kernel<<<blocks, threads>>>(out, V, idx, m, d, scale);
    }
}